// round 16
// baseline (speedup 1.0000x reference)
#include <cuda_runtime.h>
#include <cstdint>
#include <math.h>

#define BATCH     8
#define NANCH     1047552
#define KPRE      6000
#define KOUT      1000
#define SORT_N    8192
#define CHUNK2    2048
#define NCHUNK2   (SORT_N / CHUNK2)
#define WORDS     94
#define WSTRIDE   96
#define NBINS     65536
#define TILES     94
#define NSLOT     (TILES*64)
#define LRANK     2048
#define HTILES    32

typedef unsigned long long u64;

// ---------------- device scratch ----------------
__device__ __align__(128) unsigned int g_hist[NBINS];   // fallback-only
__device__ __align__(128) int          g_count[BATCH];
__device__ int g_flagB;
__device__ __align__(128) u64          g_cand[BATCH][SORT_N];    // merge ping buffer
__device__ __align__(128) u64          g_cand2[BATCH][SORT_N];   // compact + final sorted
__device__ __align__(128) float4       g_boxes[BATCH][KPRE];
__device__ __align__(128) float        g_areas[BATCH][KPRE];
__device__ __align__(128) u64          g_mask[BATCH][KPRE][WSTRIDE];
__device__ __align__(128) u64          g_rowbits[BATCH][WSTRIDE];
__device__ __align__(128) float4       g_sbox[BATCH][NSLOT];
__device__ __align__(128) float        g_sarea[BATCH][NSLOT];
__device__ __align__(128) int          g_srank[BATCH][NSLOT];
__device__ __align__(128) float4       g_aabb[BATCH][TILES];

__device__ __forceinline__ unsigned map_f32(float v) {
    unsigned b = __float_as_uint(v);
    return b ^ ((b & 0x80000000u) ? 0xFFFFFFFFu : 0x80000000u);
}

// ============ double-float exp (f32-only), bit-stable (validated R7..R15) ============
struct df { float h, l; };
__device__ __forceinline__ df df_two_sum(float a, float b) {
    float s = __fadd_rn(a, b);
    float v = __fsub_rn(s, a);
    float e = __fadd_rn(__fsub_rn(a, __fsub_rn(s, v)), __fsub_rn(b, v));
    df r; r.h = s; r.l = e; return r;
}
__device__ __forceinline__ df df_quick(float a, float b) {
    float s = __fadd_rn(a, b);
    float e = __fsub_rn(b, __fsub_rn(s, a));
    df r; r.h = s; r.l = e; return r;
}
__device__ __forceinline__ df df_add(df a, df b) {
    df s = df_two_sum(a.h, b.h);
    float e = __fadd_rn(s.l, __fadd_rn(a.l, b.l));
    return df_quick(s.h, e);
}
__device__ __forceinline__ df df_mul(df a, df b) {
    float p = __fmul_rn(a.h, b.h);
    float e = __fmaf_rn(a.h, b.h, -p);
    e = __fmaf_rn(a.h, b.l, e);
    e = __fmaf_rn(a.l, b.h, e);
    return df_quick(p, e);
}
#define DF_HI(x) ((float)(x))
#define DF_LO(x) ((float)((x) - (double)(float)(x)))
#define DF_CONST(x) { DF_HI(x), DF_LO(x) }

__device__ __forceinline__ float exp_hp(float x) {
    const float LN2H = DF_HI(0.69314718055994530941723212145818);
    const float LN2L = DF_LO(0.69314718055994530941723212145818);
    float kf = rintf(__fmul_rn(x, 1.4426950408889634f));
    float t  = __fmul_rn(kf, LN2H);
    float te = __fmaf_rn(kf, LN2H, -t);
    df r = df_two_sum(x, -t);
    r.l = __fsub_rn(r.l, __fmaf_rn(kf, LN2L, te));
    r = df_quick(r.h, r.l);
    const df C[13] = {
        DF_CONST(1.0), DF_CONST(1.0), DF_CONST(0.5),
        DF_CONST(1.0/6.0), DF_CONST(1.0/24.0), DF_CONST(1.0/120.0),
        DF_CONST(1.0/720.0), DF_CONST(1.0/5040.0), DF_CONST(1.0/40320.0),
        DF_CONST(1.0/362880.0), DF_CONST(1.0/3628800.0),
        DF_CONST(1.0/39916800.0), DF_CONST(1.0/479001600.0)
    };
    df p = C[12];
    #pragma unroll
    for (int n = 11; n >= 0; --n) p = df_add(df_mul(p, r), C[n]);
    return ldexpf(__fadd_rn(p.h, p.l), (int)kf);
}

// ---------------- K0: zero counts/flags/rowbits/mask(head rows)/cand2 --------------
__global__ void k_zero() {
    int idx = blockIdx.x * blockDim.x + threadIdx.x;
    int stride = gridDim.x * blockDim.x;
    if (idx < BATCH) g_count[idx] = 0;
    if (idx == 0) g_flagB = 0;
    u64* rb = &g_rowbits[0][0];
    for (int i = idx; i < BATCH * WSTRIDE; i += stride) rb[i] = 0ull;
    for (int i = idx; i < BATCH * LRANK * WSTRIDE; i += stride) {
        int b = i / (LRANK * WSTRIDE);
        int rem = i - b * (LRANK * WSTRIDE);
        g_mask[b][rem / WSTRIDE][rem % WSTRIDE] = 0ull;
    }
    u64* c2 = &g_cand2[0][0];
    for (int i = idx; i < BATCH * SORT_N; i += stride) c2[i] = 0ull;
}

// ---------------- K1: static-threshold compact, gated ballot (fast common path) ----
// Scores are non-negative -> float compare == mapped-uint compare; map_f32 and the
// 4-ballot sequence run only in the rare any-hit case (warp-uniform branch).
__global__ void k_compactS(const float4* __restrict__ scores4) {
    int b = blockIdx.y;
    const float fth = 0.993f;              // E[count]=7333, 15-sigma inside [6000,8192]
    const float4* sp = scores4 + (size_t)b * (NANCH / 2);
    const int M = NANCH / 2;
    int S = gridDim.x * blockDim.x;
    int tid = blockIdx.x * blockDim.x + threadIdx.x;
    int bound = ((M + 2 * S - 1) / (2 * S)) * (2 * S);
    unsigned lanebit = 1u << (threadIdx.x & 31);
    for (int i = tid; i < bound; i += 2 * S) {
        bool in0 = i < M, in1 = i + S < M;
        float s0 = -1.f, s1 = -1.f, s2 = -1.f, s3 = -1.f;
        if (in0) { float4 v = sp[i];     s0 = v.y; s1 = v.w; }
        if (in1) { float4 v = sp[i + S]; s2 = v.y; s3 = v.w; }
        bool p0 = s0 >= fth, p1 = s1 >= fth, p2 = s2 >= fth, p3 = s3 >= fth;
        unsigned any = __ballot_sync(0xffffffffu, p0 | p1 | p2 | p3);
        if (any) {
            unsigned m0 = p0 ? map_f32(s0) : 0;
            unsigned m1 = p1 ? map_f32(s1) : 0;
            unsigned m2 = p2 ? map_f32(s2) : 0;
            unsigned m3 = p3 ? map_f32(s3) : 0;
            unsigned b0 = __ballot_sync(0xffffffffu, p0);
            unsigned b1 = __ballot_sync(0xffffffffu, p1);
            unsigned b2 = __ballot_sync(0xffffffffu, p2);
            unsigned b3 = __ballot_sync(0xffffffffu, p3);
            int c0 = __popc(b0), c1 = __popc(b1), c2 = __popc(b2), c3 = __popc(b3);
            int ctot = c0 + c1 + c2 + c3;
            int base = 0;
            if ((threadIdx.x & 31) == 0) base = atomicAdd(&g_count[b], ctot);
            base = __shfl_sync(0xffffffffu, base, 0);
            if (p0) { int pos = base + __popc(b0 & (lanebit - 1));
                if (pos < SORT_N) g_cand2[b][pos] = ((u64)m0 << 32) | (u64)(0xFFFFFFFFu - (unsigned)(2 * i)); }
            if (p1) { int pos = base + c0 + __popc(b1 & (lanebit - 1));
                if (pos < SORT_N) g_cand2[b][pos] = ((u64)m1 << 32) | (u64)(0xFFFFFFFFu - (unsigned)(2 * i + 1)); }
            if (p2) { int pos = base + c0 + c1 + __popc(b2 & (lanebit - 1));
                if (pos < SORT_N) g_cand2[b][pos] = ((u64)m2 << 32) | (u64)(0xFFFFFFFFu - (unsigned)(2 * (i + S))); }
            if (p3) { int pos = base + c0 + c1 + c2 + __popc(b3 & (lanebit - 1));
                if (pos < SORT_N) g_cand2[b][pos] = ((u64)m3 << 32) | (u64)(0xFFFFFFFFu - (unsigned)(2 * (i + S) + 1)); }
        }
    }
}

// ---------------- K2: gated fallback A (self-checking, one block) ----------------
__global__ void k_fallbackA(const float4* __restrict__ scores4) {
    __shared__ int s_bad;
    int t = threadIdx.x;   // 1024
    if (t == 0) {
        int bad = 0;
        for (int bb = 0; bb < BATCH; bb++) {
            int c = g_count[bb];
            if (c < KPRE || c > SORT_N) bad = 1;
        }
        s_bad = bad;
    }
    __syncthreads();
    if (!s_bad) return;
    __shared__ unsigned s_coarse, s_fine;
    __shared__ int s_pos;
    __shared__ int fineh[256];
    const int M = NANCH / 2;
    for (int b = 0; b < BATCH; b++) {
        for (int i = t; i < NBINS; i += 1024) g_hist[i] = 0u;
        __syncthreads();
        const float4* sp = scores4 + (size_t)b * M;
        for (int i = t; i < M; i += 1024) {
            float4 v = sp[i];
            atomicAdd(&g_hist[map_f32(v.y) >> 16], 1u);
            atomicAdd(&g_hist[map_f32(v.w) >> 16], 1u);
        }
        __syncthreads();
        if (t == 0) {
            unsigned cum = 0; int bin = NBINS - 1;
            while (bin > 0 && cum + g_hist[bin] < (unsigned)KPRE) { cum += g_hist[bin]; bin--; }
            s_coarse = (unsigned)bin << 16;
        }
        if (t < 256) fineh[t] = 0;
        __syncthreads();
        unsigned coarse = s_coarse;
        for (int i = t; i < M; i += 1024) {
            float4 v = sp[i];
            unsigned mv[2] = { map_f32(v.y), map_f32(v.w) };
            #pragma unroll
            for (int q = 0; q < 2; q++) {
                if (mv[q] >= coarse) {
                    unsigned d = (mv[q] - coarse) >> 8;
                    if (d > 255) d = 255;
                    atomicAdd(&fineh[d], 1);
                }
            }
        }
        __syncthreads();
        if (t == 0) {
            int cum = 0, sb = 255;
            while (sb > 0 && cum + fineh[sb] < KPRE) { cum += fineh[sb]; sb--; }
            s_fine = coarse + ((unsigned)sb << 8);
            s_pos = 0;
        }
        __syncthreads();
        for (int i = t; i < SORT_N; i += 1024) g_cand2[b][i] = 0ull;
        __syncthreads();
        unsigned th = s_fine;
        unsigned lanebit = 1u << (t & 31);
        int bound = ((M + 1023) / 1024) * 1024;
        for (int i = t; i < bound; i += 1024) {
            bool in = i < M;
            unsigned m0 = 0, m1 = 0;
            if (in) { float4 v = sp[i]; m0 = map_f32(v.y); m1 = map_f32(v.w); }
            bool p0 = in && m0 >= th, p1 = in && m1 >= th;
            unsigned b0 = __ballot_sync(0xffffffffu, p0);
            unsigned b1 = __ballot_sync(0xffffffffu, p1);
            int c0 = __popc(b0), c1 = __popc(b1);
            if (c0 + c1) {
                int base = 0;
                if ((t & 31) == 0) base = atomicAdd(&s_pos, c0 + c1);
                base = __shfl_sync(0xffffffffu, base, 0);
                if (p0) { int pos = base + __popc(b0 & (lanebit - 1));
                    if (pos < SORT_N) g_cand2[b][pos] = ((u64)m0 << 32) | (u64)(0xFFFFFFFFu - (unsigned)(2 * i)); }
                if (p1) { int pos = base + c0 + __popc(b1 & (lanebit - 1));
                    if (pos < SORT_N) g_cand2[b][pos] = ((u64)m1 << 32) | (u64)(0xFFFFFFFFu - (unsigned)(2 * i + 1)); }
            }
        }
        __syncthreads();
    }
}

// ---------------- K3: sort 2048-key chunks of g_cand2 (descending bitonic) --------
__global__ void k_sort2048() {
    __shared__ u64 keys[CHUNK2];
    int b = blockIdx.y;
    int base = blockIdx.x * CHUNK2;
    int t = threadIdx.x;
    keys[t] = g_cand2[b][base + t];
    keys[t + 1024] = g_cand2[b][base + t + 1024];
    __syncthreads();
    for (int k = 2; k <= CHUNK2; k <<= 1) {
        for (int j = k >> 1; j > 0; j >>= 1) {
            #pragma unroll
            for (int u = 0; u < 2; u++) {
                int i = t + u * 1024;
                int ixj = i ^ j;
                if (ixj > i) {
                    bool desc = ((i & k) == 0);
                    u64 a = keys[i], c = keys[ixj];
                    if (desc ? (a < c) : (a > c)) { keys[i] = c; keys[ixj] = a; }
                }
            }
            __syncthreads();
        }
    }
    g_cand2[b][base + t] = keys[t];
    g_cand2[b][base + t + 1024] = keys[t + 1024];
}

// ---------------- K4: merge-path pass (descending, stable) ----------------
// dir=0: g_cand2 -> g_cand ; dir=1: g_cand -> g_cand2
__global__ void k_mergepass(int dir, int run) {
    int e = blockIdx.x * blockDim.x + threadIdx.x;
    int b = blockIdx.y;
    const u64* s = dir ? &g_cand[b][0] : &g_cand2[b][0];
    u64*       d = dir ? &g_cand2[b][0] : &g_cand[b][0];
    int base = e & ~(2 * run - 1);
    int local = e - base;
    u64 x = s[e];
    int pos;
    if (local < run) {
        const u64* B = s + base + run;
        int lo = 0, hi = run;
        while (lo < hi) { int mid = (lo + hi) >> 1; if (B[mid] > x) lo = mid + 1; else hi = mid; }
        pos = base + local + lo;
    } else {
        const u64* A = s + base;
        int j = local - run;
        int lo = 0, hi = run;
        while (lo < hi) { int mid = (lo + hi) >> 1; if (A[mid] >= x) lo = mid + 1; else hi = mid; }
        pos = base + lo + j;
    }
    d[pos] = x;
}

// ---------------- K5: decode boxes (reads final sorted keys in g_cand2) -----------
__global__ void k_boxes(const float4* __restrict__ deltas,
                        const float4* __restrict__ anchors) {
    int b = blockIdx.y;
    int r = blockIdx.x * blockDim.x + threadIdx.x;
    if (r >= KPRE) return;
    u64 key = g_cand2[b][r];
    unsigned idx = 0xFFFFFFFFu - (unsigned)(key & 0xFFFFFFFFull);
    if (idx >= NANCH) idx = 0;
    float4 an = anchors[idx];
    float4 dl = deltas[(size_t)b * NANCH + idx];
    float d0 = __fmul_rn(dl.x, 0.1f);
    float d1 = __fmul_rn(dl.y, 0.1f);
    float d2 = __fmul_rn(dl.z, 0.2f);
    float d3 = __fmul_rn(dl.w, 0.2f);
    float h = __fsub_rn(an.z, an.x);
    float w = __fsub_rn(an.w, an.y);
    float cy = __fadd_rn(__fadd_rn(an.x, __fmul_rn(0.5f, h)), __fmul_rn(d0, h));
    float cx = __fadd_rn(__fadd_rn(an.y, __fmul_rn(0.5f, w)), __fmul_rn(d1, w));
    float e2 = exp_hp(d2);
    float e3 = exp_hp(d3);
    float h2 = __fmul_rn(h, e2);
    float w2 = __fmul_rn(w, e3);
    float y1 = __fsub_rn(cy, __fmul_rn(0.5f, h2));
    float x1 = __fsub_rn(cx, __fmul_rn(0.5f, w2));
    float y2 = __fadd_rn(y1, h2);
    float x2 = __fadd_rn(x1, w2);
    y1 = fminf(fmaxf(y1, 0.f), 1.f);
    x1 = fminf(fmaxf(x1, 0.f), 1.f);
    y2 = fminf(fmaxf(y2, 0.f), 1.f);
    x2 = fminf(fmaxf(x2, 0.f), 1.f);
    g_boxes[b][r] = make_float4(y1, x1, y2, x2);
    g_areas[b][r] = __fmul_rn(__fsub_rn(y2, y1), __fsub_rn(x2, x1));
}

// ---------------- K6: head/tail spatial counting sort + tile AABBs (1024 thr) ------
__global__ void k_spatial() {
    int b = blockIdx.x;
    __shared__ int hist[512];
    __shared__ int offs[512];
    __shared__ unsigned short mcell[KPRE];
    int t = threadIdx.x;   // 1024
    for (int k = t; k < 512; k += blockDim.x) hist[k] = 0;
    __syncthreads();
    for (int r = t; r < KPRE; r += blockDim.x) {
        float4 bx = g_boxes[b][r];
        float cy = 0.5f * (bx.x + bx.z);
        float cx = 0.5f * (bx.y + bx.w);
        int iy = (int)(cy * 16.f); iy = iy < 0 ? 0 : (iy > 15 ? 15 : iy);
        int ix = (int)(cx * 16.f); ix = ix < 0 ? 0 : (ix > 15 ? 15 : ix);
        int m = 0;
        #pragma unroll
        for (int k = 0; k < 4; k++)
            m |= (((iy >> k) & 1) << (2 * k + 1)) | (((ix >> k) & 1) << (2 * k));
        int key = ((r < LRANK) ? 0 : 256) + m;
        mcell[r] = (unsigned short)key;
        atomicAdd(&hist[key], 1);
    }
    __syncthreads();
    if (t == 0) {
        int run = 0;
        for (int k = 0; k < 512; k++) { offs[k] = run; run += hist[k]; }
    }
    __syncthreads();
    for (int r = t; r < KPRE; r += blockDim.x) {
        int key = mcell[r];
        int pos = atomicAdd(&offs[key], 1);
        g_sbox[b][pos] = g_boxes[b][r];
        g_sarea[b][pos] = g_areas[b][r];
        g_srank[b][pos] = r;
    }
    if (t < NSLOT - KPRE) {
        int pos = KPRE + t;
        g_sbox[b][pos] = make_float4(9e9f, 9e9f, -9e9f, -9e9f);
        g_sarea[b][pos] = 0.f;
        g_srank[b][pos] = 0;
    }
    __syncthreads();
    if (t < TILES) {
        float miny = 9e9f, minx = 9e9f, maxy = -9e9f, maxx = -9e9f;
        #pragma unroll 4
        for (int e = 0; e < 64; e++) {
            float4 bx = g_sbox[b][t * 64 + e];
            miny = fminf(miny, bx.x); minx = fminf(minx, bx.y);
            maxy = fmaxf(maxy, bx.z); maxx = fmaxf(maxx, bx.w);
        }
        g_aabb[b][t] = make_float4(miny, minx, maxy, maxx);
    }
}

// ---------------- IoU pair body (single tile pair) ----------------
__device__ __forceinline__ void pair_tiles(int b, int ta, int tb) {
    float4 aA = g_aabb[b][ta];
    float4 aB = g_aabb[b][tb];
    if (!(aA.z > aB.x && aB.z > aA.x && aA.w > aB.y && aB.w > aA.y)) return;
    __shared__ float4 sb4[64];
    __shared__ float  sar[64];
    __shared__ int    srk[64];
    int t = threadIdx.x;
    int row = t & 63;
    int half = t >> 6;
    if (t < 64) {
        int s = tb * 64 + t;
        sb4[t] = g_sbox[b][s];
        sar[t] = g_sarea[b][s];
        srk[t] = g_srank[b][s];
    }
    __syncthreads();
    int sa = ta * 64 + row;
    float4 bi = g_sbox[b][sa];
    float  ai = g_sarea[b][sa];
    int ra = g_srank[b][sa];
    if (!(bi.z > aB.x && aB.z > bi.x && bi.w > aB.y && aB.w > bi.y)) return;
    bool diag = (ta == tb);
    int j0 = half * 32;
    #pragma unroll 4
    for (int jj = j0; jj < j0 + 32; ++jj) {
        if (diag && jj <= row) continue;
        float4 bj = sb4[jj];
        float yy1 = fmaxf(bi.x, bj.x);
        float xx1 = fmaxf(bi.y, bj.y);
        float yy2 = fminf(bi.z, bj.z);
        float xx2 = fminf(bi.w, bj.w);
        float dh = __fsub_rn(yy2, yy1);
        float dw = __fsub_rn(xx2, xx1);
        if (dh > 0.f && dw > 0.f) {
            float inter = __fmul_rn(dh, dw);
            float u = __fsub_rn(__fadd_rn(ai, sar[jj]), inter);
            if (u > 0.f) {
                bool sup;
                if (inter > __fmul_rn(0.71f, u)) sup = true;
                else if (inter >= __fmul_rn(0.69f, u)) sup = __fdiv_rn(inter, u) > 0.7f;
                else sup = false;
                if (sup) {
                    int rb = srk[jj];
                    int rmin = ra < rb ? ra : rb;
                    int rmax = ra < rb ? rb : ra;
                    atomicOr(&g_mask[b][rmin][rmax >> 6], 1ull << (rmax & 63));
                    atomicOr(&g_rowbits[b][rmin >> 6], 1ull << (rmin & 63));
                }
            }
        }
    }
}

// ---------------- K7: pairs with at least one head tile ----------------
__global__ void k_pairs() {
    int ta = blockIdx.x;
    int hb = blockIdx.y;
    if (ta < hb) return;
    pair_tiles(blockIdx.z, ta, hb);
}

// ---------------- warp-level greedy reduce (bulk selection + prefetch) ------------
__device__ void reduce_core(int b, int lane, int* sel, float* __restrict__ out, int setflag) {
    u64 rm0 = 0ull, rm1 = 0ull, rm2 = 0ull;
    const u64* mask = &g_mask[b][0][0];
    u64 hb0 = g_rowbits[b][lane];
    u64 hb1 = g_rowbits[b][lane + 32];
    u64 hb2 = (lane + 64 < WORDS) ? g_rowbits[b][lane + 64] : 0ull;
    int cnt = 0;

    for (int w = 0; w < WORDS && cnt < KOUT; ++w) {
        int slot = w >> 5, owner = w & 31;
        u64 rmv = (slot == 0) ? rm0 : ((slot == 1) ? rm1 : rm2);
        u64 hbv = (slot == 0) ? hb0 : ((slot == 1) ? hb1 : hb2);
        u64 cur = __shfl_sync(0xffffffffu, rmv, owner);
        u64 hasw = __shfl_sync(0xffffffffu, hbv, owner);
        if (w == WORDS - 1) cur |= ~((1ull << 48) - 1);

        {
            u64 pf = ~cur & hasw;
            #pragma unroll
            for (int c = 0; c < 3; c++) {
                if (!pf) break;
                int nb = __ffsll((long long)pf) - 1;
                pf &= pf - 1;
                const char* p = (const char*)(mask + (size_t)((w << 6) + nb) * WSTRIDE);
                if ((lane >> 3) == c && (lane & 7) < 6)
                    asm volatile("prefetch.global.L1 [%0];" :: "l"(p + (lane & 7) * 128));
            }
        }

        while (cnt < KOUT) {
            u64 valid = ~cur;
            if (!valid) break;
            u64 sup = valid & hasw;
            u64 below = sup ? ((sup & (0ull - sup)) - 1ull) : ~0ull;
            u64 bulk = valid & below;
            int n = __popcll(bulk);
            int take = n < (KOUT - cnt) ? n : (KOUT - cnt);
            if (take > 0) {
                if (lane == 0) {
                    u64 tb = bulk;
                    int base_ = (w << 6);
                    for (int k = 0; k < take; k++) {
                        int bp = __ffsll((long long)tb) - 1;
                        sel[cnt + k] = base_ + bp;
                        tb &= tb - 1;
                    }
                    if (setflag && w >= (LRANK >> 6)) g_flagB = 1;
                }
                cnt += take;
                cur |= bulk;
                if (cnt >= KOUT) break;
            }
            if (!sup) break;
            int bpos = __ffsll((long long)sup) - 1;
            int i = (w << 6) + bpos;
            if (lane == 0) {
                sel[cnt] = i;
                if (setflag && i >= LRANK) g_flagB = 1;
            }
            cnt++;
            cur |= (1ull << bpos);
            if (cnt >= KOUT) break;
            const u64* rowp = mask + (size_t)i * WSTRIDE;
            u64 r0 = __ldg(rowp + lane);
            u64 r1 = __ldg(rowp + lane + 32);
            u64 r2 = (lane + 64 < WORDS) ? __ldg(rowp + lane + 64) : 0ull;
            u64 rcur = __ldg(rowp + w);
            rm0 |= r0; rm1 |= r1; rm2 |= r2;
            cur |= rcur;
            u64 pf = ~cur & hasw;
            #pragma unroll
            for (int c = 0; c < 2; c++) {
                if (!pf) break;
                int nb = __ffsll((long long)pf) - 1;
                pf &= pf - 1;
                const char* p = (const char*)(mask + (size_t)((w << 6) + nb) * WSTRIDE);
                if ((lane >> 3) == c && (lane & 7) < 6)
                    asm volatile("prefetch.global.L1 [%0];" :: "l"(p + (lane & 7) * 128));
            }
        }
    }
    __syncwarp();

    float4* o = (float4*)(out + (size_t)b * KOUT * 4);
    for (int r = lane; r < KOUT; r += 32) {
        float4 v = make_float4(0.f, 0.f, 0.f, 0.f);
        if (r < cnt) v = g_boxes[b][sel[r]];
        o[r] = v;
    }
}

// ---------------- K8: primary reduce (1 warp per batch) ----------------
__global__ void k_reduce(float* __restrict__ out) {
    __shared__ int sel[KOUT];
    reduce_core(blockIdx.x, threadIdx.x, sel, out, 1);
}

// ---------------- K9: gated fallback B — zero tail, tail pairs, full redo ---------
__global__ void k_fallbackB(float* __restrict__ out) {
    if (!g_flagB) return;
    int t = threadIdx.x;   // 1024
    const int n = BATCH * (KPRE - LRANK) * WSTRIDE;
    for (int i = t; i < n; i += 1024) {
        int b = i / ((KPRE - LRANK) * WSTRIDE);
        int rem = i - b * ((KPRE - LRANK) * WSTRIDE);
        g_mask[b][LRANK + rem / WSTRIDE][rem % WSTRIDE] = 0ull;
    }
    __syncthreads();
    __shared__ float4 sb4[64];
    __shared__ float  sar[64];
    __shared__ int    srk[64];
    int row = t & 63;
    int half = (t >> 6) & 1;
    for (int b = 0; b < BATCH; b++) {
        for (int ta = HTILES; ta < TILES; ta++) {
            float4 aA = g_aabb[b][ta];
            float4 bi = make_float4(0, 0, 0, 0);
            float ai = 0.f; int ra = 0;
            if (t < 128) {
                int sa = ta * 64 + row;
                bi = g_sbox[b][sa]; ai = g_sarea[b][sa]; ra = g_srank[b][sa];
            }
            for (int tb = ta; tb < TILES; tb++) {
                float4 aB = g_aabb[b][tb];
                bool tok = (aA.z > aB.x && aB.z > aA.x && aA.w > aB.y && aB.w > aA.y);
                __syncthreads();
                if (tok && t < 64) {
                    int s = tb * 64 + t;
                    sb4[t] = g_sbox[b][s]; sar[t] = g_sarea[b][s]; srk[t] = g_srank[b][s];
                }
                __syncthreads();
                if (!tok || t >= 128) continue;
                if (!(bi.z > aB.x && aB.z > bi.x && bi.w > aB.y && aB.w > bi.y)) continue;
                bool diag = (ta == tb);
                for (int jj = half * 32; jj < half * 32 + 32; ++jj) {
                    if (diag && jj <= row) continue;
                    float4 bj = sb4[jj];
                    float yy1 = fmaxf(bi.x, bj.x);
                    float xx1 = fmaxf(bi.y, bj.y);
                    float yy2 = fminf(bi.z, bj.z);
                    float xx2 = fminf(bi.w, bj.w);
                    float dh = __fsub_rn(yy2, yy1);
                    float dw = __fsub_rn(xx2, xx1);
                    if (dh > 0.f && dw > 0.f) {
                        float inter = __fmul_rn(dh, dw);
                        float u = __fsub_rn(__fadd_rn(ai, sar[jj]), inter);
                        if (u > 0.f) {
                            bool sup;
                            if (inter > __fmul_rn(0.71f, u)) sup = true;
                            else if (inter >= __fmul_rn(0.69f, u)) sup = __fdiv_rn(inter, u) > 0.7f;
                            else sup = false;
                            if (sup) {
                                int rb = srk[jj];
                                int rmin = ra < rb ? ra : rb;
                                int rmax = ra < rb ? rb : ra;
                                atomicOr(&g_mask[b][rmin][rmax >> 6], 1ull << (rmax & 63));
                                atomicOr(&g_rowbits[b][rmin >> 6], 1ull << (rmin & 63));
                            }
                        }
                    }
                }
            }
        }
    }
    __threadfence();
    __syncthreads();
    __shared__ int sel[BATCH][KOUT];
    int wid = t >> 5, lane = t & 31;
    if (wid < BATCH) reduce_core(wid, lane, sel[wid], out, 0);
}

// ---------------- launch (11 graph nodes) ----------------
extern "C" void kernel_launch(void* const* d_in, const int* in_sizes, int n_in,
                              void* d_out, int out_size) {
    const float4* scores4 = (const float4*)d_in[0];
    const float4* deltas  = (const float4*)d_in[1];
    const float4* anchors = (const float4*)d_in[2];
    float* out = (float*)d_out;

    k_zero<<<512, 1024>>>();                    // 1
    {
        dim3 g(256, BATCH);
        k_compactS<<<g, 256>>>(scores4);        // 2
    }
    k_fallbackA<<<1, 1024>>>(scores4);          // 3 (self-gated)
    {
        dim3 g(NCHUNK2, BATCH);
        k_sort2048<<<g, 1024>>>();              // 4
    }
    {
        dim3 g(SORT_N / 256, BATCH);
        k_mergepass<<<g, 256>>>(0, 2048);       // 5: cand2 -> cand
        k_mergepass<<<g, 256>>>(1, 4096);       // 6: cand -> cand2 (final sorted)
    }
    {
        dim3 g((KPRE + 255) / 256, BATCH);
        k_boxes<<<g, 256>>>(deltas, anchors);   // 7
    }
    k_spatial<<<BATCH, 1024>>>();               // 8
    {
        dim3 g(TILES, HTILES, BATCH);
        k_pairs<<<g, 128>>>();                  // 9
    }
    k_reduce<<<BATCH, 32>>>(out);               // 10
    k_fallbackB<<<1, 1024>>>(out);              // 11 (gated)
}

// round 17
// speedup vs baseline: 1.0280x; 1.0280x over previous
#include <cuda_runtime.h>
#include <cstdint>
#include <math.h>

#define BATCH     8
#define NANCH     1047552
#define KPRE      6000
#define KOUT      1000
#define SORT_N    8192
#define CHUNK2    2048
#define NCHUNK2   (SORT_N / CHUNK2)
#define WORDS     94
#define WSTRIDE   96
#define NBINS     65536
#define TILES     94
#define NSLOT     (TILES*64)
#define LRANK     2048
#define HTILES    32

typedef unsigned long long u64;

// ---------------- device scratch ----------------
__device__ __align__(128) unsigned int g_hist[NBINS];   // fallback-only
__device__ __align__(128) int          g_count[BATCH];
__device__ int g_flagB;
__device__ __align__(128) u64          g_cand[BATCH][SORT_N];    // merge ping buffer
__device__ __align__(128) u64          g_cand2[BATCH][SORT_N];   // compact + final sorted
__device__ __align__(128) float4       g_boxes[BATCH][KPRE];
__device__ __align__(128) float        g_areas[BATCH][KPRE];
__device__ __align__(128) u64          g_mask[BATCH][KPRE][WSTRIDE];
__device__ __align__(128) u64          g_rowbits[BATCH][WSTRIDE];
__device__ __align__(128) float4       g_sbox[BATCH][NSLOT];
__device__ __align__(128) float        g_sarea[BATCH][NSLOT];
__device__ __align__(128) int          g_srank[BATCH][NSLOT];
__device__ __align__(128) float4       g_aabb[BATCH][TILES];

__device__ __forceinline__ unsigned map_f32(float v) {
    unsigned b = __float_as_uint(v);
    return b ^ ((b & 0x80000000u) ? 0xFFFFFFFFu : 0x80000000u);
}

// ============ double-float exp (f32-only), bit-stable (validated R7..R16) ============
struct df { float h, l; };
__device__ __forceinline__ df df_two_sum(float a, float b) {
    float s = __fadd_rn(a, b);
    float v = __fsub_rn(s, a);
    float e = __fadd_rn(__fsub_rn(a, __fsub_rn(s, v)), __fsub_rn(b, v));
    df r; r.h = s; r.l = e; return r;
}
__device__ __forceinline__ df df_quick(float a, float b) {
    float s = __fadd_rn(a, b);
    float e = __fsub_rn(b, __fsub_rn(s, a));
    df r; r.h = s; r.l = e; return r;
}
__device__ __forceinline__ df df_add(df a, df b) {
    df s = df_two_sum(a.h, b.h);
    float e = __fadd_rn(s.l, __fadd_rn(a.l, b.l));
    return df_quick(s.h, e);
}
__device__ __forceinline__ df df_mul(df a, df b) {
    float p = __fmul_rn(a.h, b.h);
    float e = __fmaf_rn(a.h, b.h, -p);
    e = __fmaf_rn(a.h, b.l, e);
    e = __fmaf_rn(a.l, b.h, e);
    return df_quick(p, e);
}
#define DF_HI(x) ((float)(x))
#define DF_LO(x) ((float)((x) - (double)(float)(x)))
#define DF_CONST(x) { DF_HI(x), DF_LO(x) }

__device__ __forceinline__ float exp_hp(float x) {
    const float LN2H = DF_HI(0.69314718055994530941723212145818);
    const float LN2L = DF_LO(0.69314718055994530941723212145818);
    float kf = rintf(__fmul_rn(x, 1.4426950408889634f));
    float t  = __fmul_rn(kf, LN2H);
    float te = __fmaf_rn(kf, LN2H, -t);
    df r = df_two_sum(x, -t);
    r.l = __fsub_rn(r.l, __fmaf_rn(kf, LN2L, te));
    r = df_quick(r.h, r.l);
    const df C[13] = {
        DF_CONST(1.0), DF_CONST(1.0), DF_CONST(0.5),
        DF_CONST(1.0/6.0), DF_CONST(1.0/24.0), DF_CONST(1.0/120.0),
        DF_CONST(1.0/720.0), DF_CONST(1.0/5040.0), DF_CONST(1.0/40320.0),
        DF_CONST(1.0/362880.0), DF_CONST(1.0/3628800.0),
        DF_CONST(1.0/39916800.0), DF_CONST(1.0/479001600.0)
    };
    df p = C[12];
    #pragma unroll
    for (int n = 11; n >= 0; --n) p = df_add(df_mul(p, r), C[n]);
    return ldexpf(__fadd_rn(p.h, p.l), (int)kf);
}

// ---------------- K0: zero counts/flags/rowbits/mask(head rows)/cand2 --------------
__global__ void k_zero() {
    int idx = blockIdx.x * blockDim.x + threadIdx.x;
    int stride = gridDim.x * blockDim.x;
    if (idx < BATCH) g_count[idx] = 0;
    if (idx == 0) g_flagB = 0;
    u64* rb = &g_rowbits[0][0];
    for (int i = idx; i < BATCH * WSTRIDE; i += stride) rb[i] = 0ull;
    for (int i = idx; i < BATCH * LRANK * WSTRIDE; i += stride) {
        int b = i / (LRANK * WSTRIDE);
        int rem = i - b * (LRANK * WSTRIDE);
        g_mask[b][rem / WSTRIDE][rem % WSTRIDE] = 0ull;
    }
    u64* c2 = &g_cand2[0][0];
    for (int i = idx; i < BATCH * SORT_N; i += stride) c2[i] = 0ull;
}

// ---------------- K1: static-threshold (0.993) compact (champion ballot body) ------
__global__ void k_compactS(const float4* __restrict__ scores4) {
    int b = blockIdx.y;
    const unsigned th = map_f32(0.993f);   // E[count]=7333, 15-sigma inside [6000,8192]
    const float4* sp = scores4 + (size_t)b * (NANCH / 2);
    const int M = NANCH / 2;
    int S = gridDim.x * blockDim.x;
    int tid = blockIdx.x * blockDim.x + threadIdx.x;
    int bound = ((M + 2 * S - 1) / (2 * S)) * (2 * S);
    unsigned lanebit = 1u << (threadIdx.x & 31);
    for (int i = tid; i < bound; i += 2 * S) {
        bool in0 = i < M, in1 = i + S < M;
        unsigned m0 = 0, m1 = 0, m2 = 0, m3 = 0;
        if (in0) { float4 v = sp[i];     m0 = map_f32(v.y); m1 = map_f32(v.w); }
        if (in1) { float4 v = sp[i + S]; m2 = map_f32(v.y); m3 = map_f32(v.w); }
        bool p0 = in0 && m0 >= th, p1 = in0 && m1 >= th;
        bool p2 = in1 && m2 >= th, p3 = in1 && m3 >= th;
        unsigned b0 = __ballot_sync(0xffffffffu, p0);
        unsigned b1 = __ballot_sync(0xffffffffu, p1);
        unsigned b2 = __ballot_sync(0xffffffffu, p2);
        unsigned b3 = __ballot_sync(0xffffffffu, p3);
        int c0 = __popc(b0), c1 = __popc(b1), c2 = __popc(b2), c3 = __popc(b3);
        int ctot = c0 + c1 + c2 + c3;
        if (ctot) {
            int base = 0;
            if ((threadIdx.x & 31) == 0) base = atomicAdd(&g_count[b], ctot);
            base = __shfl_sync(0xffffffffu, base, 0);
            if (p0) { int pos = base + __popc(b0 & (lanebit - 1));
                if (pos < SORT_N) g_cand2[b][pos] = ((u64)m0 << 32) | (u64)(0xFFFFFFFFu - (unsigned)(2 * i)); }
            if (p1) { int pos = base + c0 + __popc(b1 & (lanebit - 1));
                if (pos < SORT_N) g_cand2[b][pos] = ((u64)m1 << 32) | (u64)(0xFFFFFFFFu - (unsigned)(2 * i + 1)); }
            if (p2) { int pos = base + c0 + c1 + __popc(b2 & (lanebit - 1));
                if (pos < SORT_N) g_cand2[b][pos] = ((u64)m2 << 32) | (u64)(0xFFFFFFFFu - (unsigned)(2 * (i + S))); }
            if (p3) { int pos = base + c0 + c1 + c2 + __popc(b3 & (lanebit - 1));
                if (pos < SORT_N) g_cand2[b][pos] = ((u64)m3 << 32) | (u64)(0xFFFFFFFFu - (unsigned)(2 * (i + S) + 1)); }
        }
    }
}

// ---------------- K2: gated fallback A (self-checking, one block) ----------------
__global__ void k_fallbackA(const float4* __restrict__ scores4) {
    __shared__ int s_bad;
    int t = threadIdx.x;   // 1024
    if (t == 0) {
        int bad = 0;
        for (int bb = 0; bb < BATCH; bb++) {
            int c = g_count[bb];
            if (c < KPRE || c > SORT_N) bad = 1;
        }
        s_bad = bad;
    }
    __syncthreads();
    if (!s_bad) return;
    __shared__ unsigned s_coarse, s_fine;
    __shared__ int s_pos;
    __shared__ int fineh[256];
    const int M = NANCH / 2;
    for (int b = 0; b < BATCH; b++) {
        for (int i = t; i < NBINS; i += 1024) g_hist[i] = 0u;
        __syncthreads();
        const float4* sp = scores4 + (size_t)b * M;
        for (int i = t; i < M; i += 1024) {
            float4 v = sp[i];
            atomicAdd(&g_hist[map_f32(v.y) >> 16], 1u);
            atomicAdd(&g_hist[map_f32(v.w) >> 16], 1u);
        }
        __syncthreads();
        if (t == 0) {
            unsigned cum = 0; int bin = NBINS - 1;
            while (bin > 0 && cum + g_hist[bin] < (unsigned)KPRE) { cum += g_hist[bin]; bin--; }
            s_coarse = (unsigned)bin << 16;
        }
        if (t < 256) fineh[t] = 0;
        __syncthreads();
        unsigned coarse = s_coarse;
        for (int i = t; i < M; i += 1024) {
            float4 v = sp[i];
            unsigned mv[2] = { map_f32(v.y), map_f32(v.w) };
            #pragma unroll
            for (int q = 0; q < 2; q++) {
                if (mv[q] >= coarse) {
                    unsigned d = (mv[q] - coarse) >> 8;
                    if (d > 255) d = 255;
                    atomicAdd(&fineh[d], 1);
                }
            }
        }
        __syncthreads();
        if (t == 0) {
            int cum = 0, sb = 255;
            while (sb > 0 && cum + fineh[sb] < KPRE) { cum += fineh[sb]; sb--; }
            s_fine = coarse + ((unsigned)sb << 8);
            s_pos = 0;
        }
        __syncthreads();
        for (int i = t; i < SORT_N; i += 1024) g_cand2[b][i] = 0ull;
        __syncthreads();
        unsigned th = s_fine;
        unsigned lanebit = 1u << (t & 31);
        int bound = ((M + 1023) / 1024) * 1024;
        for (int i = t; i < bound; i += 1024) {
            bool in = i < M;
            unsigned m0 = 0, m1 = 0;
            if (in) { float4 v = sp[i]; m0 = map_f32(v.y); m1 = map_f32(v.w); }
            bool p0 = in && m0 >= th, p1 = in && m1 >= th;
            unsigned b0 = __ballot_sync(0xffffffffu, p0);
            unsigned b1 = __ballot_sync(0xffffffffu, p1);
            int c0 = __popc(b0), c1 = __popc(b1);
            if (c0 + c1) {
                int base = 0;
                if ((t & 31) == 0) base = atomicAdd(&s_pos, c0 + c1);
                base = __shfl_sync(0xffffffffu, base, 0);
                if (p0) { int pos = base + __popc(b0 & (lanebit - 1));
                    if (pos < SORT_N) g_cand2[b][pos] = ((u64)m0 << 32) | (u64)(0xFFFFFFFFu - (unsigned)(2 * i)); }
                if (p1) { int pos = base + c0 + __popc(b1 & (lanebit - 1));
                    if (pos < SORT_N) g_cand2[b][pos] = ((u64)m1 << 32) | (u64)(0xFFFFFFFFu - (unsigned)(2 * i + 1)); }
            }
        }
        __syncthreads();
    }
}

// ---------------- K3: sort 2048-key chunks of g_cand2 (descending bitonic) --------
__global__ void k_sort2048() {
    __shared__ u64 keys[CHUNK2];
    int b = blockIdx.y;
    int base = blockIdx.x * CHUNK2;
    int t = threadIdx.x;
    keys[t] = g_cand2[b][base + t];
    keys[t + 1024] = g_cand2[b][base + t + 1024];
    __syncthreads();
    for (int k = 2; k <= CHUNK2; k <<= 1) {
        for (int j = k >> 1; j > 0; j >>= 1) {
            #pragma unroll
            for (int u = 0; u < 2; u++) {
                int i = t + u * 1024;
                int ixj = i ^ j;
                if (ixj > i) {
                    bool desc = ((i & k) == 0);
                    u64 a = keys[i], c = keys[ixj];
                    if (desc ? (a < c) : (a > c)) { keys[i] = c; keys[ixj] = a; }
                }
            }
            __syncthreads();
        }
    }
    g_cand2[b][base + t] = keys[t];
    g_cand2[b][base + t + 1024] = keys[t + 1024];
}

// ---------------- K4: merge-path pass (descending, stable) ----------------
// dir=0: g_cand2 -> g_cand ; dir=1: g_cand -> g_cand2
__global__ void k_mergepass(int dir, int run) {
    int e = blockIdx.x * blockDim.x + threadIdx.x;
    int b = blockIdx.y;
    const u64* s = dir ? &g_cand[b][0] : &g_cand2[b][0];
    u64*       d = dir ? &g_cand2[b][0] : &g_cand[b][0];
    int base = e & ~(2 * run - 1);
    int local = e - base;
    u64 x = s[e];
    int pos;
    if (local < run) {
        const u64* B = s + base + run;
        int lo = 0, hi = run;
        while (lo < hi) { int mid = (lo + hi) >> 1; if (B[mid] > x) lo = mid + 1; else hi = mid; }
        pos = base + local + lo;
    } else {
        const u64* A = s + base;
        int j = local - run;
        int lo = 0, hi = run;
        while (lo < hi) { int mid = (lo + hi) >> 1; if (A[mid] >= x) lo = mid + 1; else hi = mid; }
        pos = base + lo + j;
    }
    d[pos] = x;
}

// ---------------- K5: decode boxes (reads final sorted keys in g_cand2) -----------
__global__ void k_boxes(const float4* __restrict__ deltas,
                        const float4* __restrict__ anchors) {
    int b = blockIdx.y;
    int r = blockIdx.x * blockDim.x + threadIdx.x;
    if (r >= KPRE) return;
    u64 key = g_cand2[b][r];
    unsigned idx = 0xFFFFFFFFu - (unsigned)(key & 0xFFFFFFFFull);
    if (idx >= NANCH) idx = 0;
    float4 an = anchors[idx];
    float4 dl = deltas[(size_t)b * NANCH + idx];
    float d0 = __fmul_rn(dl.x, 0.1f);
    float d1 = __fmul_rn(dl.y, 0.1f);
    float d2 = __fmul_rn(dl.z, 0.2f);
    float d3 = __fmul_rn(dl.w, 0.2f);
    float h = __fsub_rn(an.z, an.x);
    float w = __fsub_rn(an.w, an.y);
    float cy = __fadd_rn(__fadd_rn(an.x, __fmul_rn(0.5f, h)), __fmul_rn(d0, h));
    float cx = __fadd_rn(__fadd_rn(an.y, __fmul_rn(0.5f, w)), __fmul_rn(d1, w));
    float e2 = exp_hp(d2);
    float e3 = exp_hp(d3);
    float h2 = __fmul_rn(h, e2);
    float w2 = __fmul_rn(w, e3);
    float y1 = __fsub_rn(cy, __fmul_rn(0.5f, h2));
    float x1 = __fsub_rn(cx, __fmul_rn(0.5f, w2));
    float y2 = __fadd_rn(y1, h2);
    float x2 = __fadd_rn(x1, w2);
    y1 = fminf(fmaxf(y1, 0.f), 1.f);
    x1 = fminf(fmaxf(x1, 0.f), 1.f);
    y2 = fminf(fmaxf(y2, 0.f), 1.f);
    x2 = fminf(fmaxf(x2, 0.f), 1.f);
    g_boxes[b][r] = make_float4(y1, x1, y2, x2);
    g_areas[b][r] = __fmul_rn(__fsub_rn(y2, y1), __fsub_rn(x2, x1));
}

// ---------------- K6: head/tail spatial counting sort + tile AABBs (1024 thr) ------
// Prefix scan of the 512 bins is Hillis-Steele parallel (was serial on thread 0).
__global__ void k_spatial() {
    int b = blockIdx.x;
    __shared__ int hist[512];
    __shared__ int scan[512];
    __shared__ int offs[512];
    __shared__ unsigned short mcell[KPRE];
    int t = threadIdx.x;   // 1024
    for (int k = t; k < 512; k += blockDim.x) hist[k] = 0;
    __syncthreads();
    for (int r = t; r < KPRE; r += blockDim.x) {
        float4 bx = g_boxes[b][r];
        float cy = 0.5f * (bx.x + bx.z);
        float cx = 0.5f * (bx.y + bx.w);
        int iy = (int)(cy * 16.f); iy = iy < 0 ? 0 : (iy > 15 ? 15 : iy);
        int ix = (int)(cx * 16.f); ix = ix < 0 ? 0 : (ix > 15 ? 15 : ix);
        int m = 0;
        #pragma unroll
        for (int k = 0; k < 4; k++)
            m |= (((iy >> k) & 1) << (2 * k + 1)) | (((ix >> k) & 1) << (2 * k));
        int key = ((r < LRANK) ? 0 : 256) + m;
        mcell[r] = (unsigned short)key;
        atomicAdd(&hist[key], 1);
    }
    __syncthreads();
    // exclusive scan of hist -> offs (Hillis-Steele inclusive, then subtract self)
    if (t < 512) scan[t] = hist[t];
    __syncthreads();
    #pragma unroll
    for (int off = 1; off < 512; off <<= 1) {
        int v = 0;
        if (t < 512 && t >= off) v = scan[t - off];
        __syncthreads();
        if (t < 512) scan[t] += v;
        __syncthreads();
    }
    if (t < 512) offs[t] = scan[t] - hist[t];
    __syncthreads();
    for (int r = t; r < KPRE; r += blockDim.x) {
        int key = mcell[r];
        int pos = atomicAdd(&offs[key], 1);
        g_sbox[b][pos] = g_boxes[b][r];
        g_sarea[b][pos] = g_areas[b][r];
        g_srank[b][pos] = r;
    }
    if (t < NSLOT - KPRE) {
        int pos = KPRE + t;
        g_sbox[b][pos] = make_float4(9e9f, 9e9f, -9e9f, -9e9f);
        g_sarea[b][pos] = 0.f;
        g_srank[b][pos] = 0;
    }
    __syncthreads();
    if (t < TILES) {
        float miny = 9e9f, minx = 9e9f, maxy = -9e9f, maxx = -9e9f;
        #pragma unroll 4
        for (int e = 0; e < 64; e++) {
            float4 bx = g_sbox[b][t * 64 + e];
            miny = fminf(miny, bx.x); minx = fminf(minx, bx.y);
            maxy = fmaxf(maxy, bx.z); maxx = fmaxf(maxx, bx.w);
        }
        g_aabb[b][t] = make_float4(miny, minx, maxy, maxx);
    }
}

// ---------------- IoU pair body (single tile pair) ----------------
__device__ __forceinline__ void pair_tiles(int b, int ta, int tb) {
    float4 aA = g_aabb[b][ta];
    float4 aB = g_aabb[b][tb];
    if (!(aA.z > aB.x && aB.z > aA.x && aA.w > aB.y && aB.w > aA.y)) return;
    __shared__ float4 sb4[64];
    __shared__ float  sar[64];
    __shared__ int    srk[64];
    int t = threadIdx.x;
    int row = t & 63;
    int half = t >> 6;
    if (t < 64) {
        int s = tb * 64 + t;
        sb4[t] = g_sbox[b][s];
        sar[t] = g_sarea[b][s];
        srk[t] = g_srank[b][s];
    }
    __syncthreads();
    int sa = ta * 64 + row;
    float4 bi = g_sbox[b][sa];
    float  ai = g_sarea[b][sa];
    int ra = g_srank[b][sa];
    if (!(bi.z > aB.x && aB.z > bi.x && bi.w > aB.y && aB.w > bi.y)) return;
    bool diag = (ta == tb);
    int j0 = half * 32;
    #pragma unroll 4
    for (int jj = j0; jj < j0 + 32; ++jj) {
        if (diag && jj <= row) continue;
        float4 bj = sb4[jj];
        float yy1 = fmaxf(bi.x, bj.x);
        float xx1 = fmaxf(bi.y, bj.y);
        float yy2 = fminf(bi.z, bj.z);
        float xx2 = fminf(bi.w, bj.w);
        float dh = __fsub_rn(yy2, yy1);
        float dw = __fsub_rn(xx2, xx1);
        if (dh > 0.f && dw > 0.f) {
            float inter = __fmul_rn(dh, dw);
            float u = __fsub_rn(__fadd_rn(ai, sar[jj]), inter);
            if (u > 0.f) {
                bool sup;
                if (inter > __fmul_rn(0.71f, u)) sup = true;
                else if (inter >= __fmul_rn(0.69f, u)) sup = __fdiv_rn(inter, u) > 0.7f;
                else sup = false;
                if (sup) {
                    int rb = srk[jj];
                    int rmin = ra < rb ? ra : rb;
                    int rmax = ra < rb ? rb : ra;
                    atomicOr(&g_mask[b][rmin][rmax >> 6], 1ull << (rmax & 63));
                    atomicOr(&g_rowbits[b][rmin >> 6], 1ull << (rmin & 63));
                }
            }
        }
    }
}

// ---------------- K7: pairs with at least one head tile ----------------
__global__ void k_pairs() {
    int ta = blockIdx.x;
    int hb = blockIdx.y;
    if (ta < hb) return;
    pair_tiles(blockIdx.z, ta, hb);
}

// ---------------- warp-level greedy reduce (bulk selection + prefetch) ------------
__device__ void reduce_core(int b, int lane, int* sel, float* __restrict__ out, int setflag) {
    u64 rm0 = 0ull, rm1 = 0ull, rm2 = 0ull;
    const u64* mask = &g_mask[b][0][0];
    u64 hb0 = g_rowbits[b][lane];
    u64 hb1 = g_rowbits[b][lane + 32];
    u64 hb2 = (lane + 64 < WORDS) ? g_rowbits[b][lane + 64] : 0ull;
    int cnt = 0;

    for (int w = 0; w < WORDS && cnt < KOUT; ++w) {
        int slot = w >> 5, owner = w & 31;
        u64 rmv = (slot == 0) ? rm0 : ((slot == 1) ? rm1 : rm2);
        u64 hbv = (slot == 0) ? hb0 : ((slot == 1) ? hb1 : hb2);
        u64 cur = __shfl_sync(0xffffffffu, rmv, owner);
        u64 hasw = __shfl_sync(0xffffffffu, hbv, owner);
        if (w == WORDS - 1) cur |= ~((1ull << 48) - 1);

        {
            u64 pf = ~cur & hasw;
            #pragma unroll
            for (int c = 0; c < 3; c++) {
                if (!pf) break;
                int nb = __ffsll((long long)pf) - 1;
                pf &= pf - 1;
                const char* p = (const char*)(mask + (size_t)((w << 6) + nb) * WSTRIDE);
                if ((lane >> 3) == c && (lane & 7) < 6)
                    asm volatile("prefetch.global.L1 [%0];" :: "l"(p + (lane & 7) * 128));
            }
        }

        while (cnt < KOUT) {
            u64 valid = ~cur;
            if (!valid) break;
            u64 sup = valid & hasw;
            u64 below = sup ? ((sup & (0ull - sup)) - 1ull) : ~0ull;
            u64 bulk = valid & below;
            int n = __popcll(bulk);
            int take = n < (KOUT - cnt) ? n : (KOUT - cnt);
            if (take > 0) {
                if (lane == 0) {
                    u64 tb = bulk;
                    int base_ = (w << 6);
                    for (int k = 0; k < take; k++) {
                        int bp = __ffsll((long long)tb) - 1;
                        sel[cnt + k] = base_ + bp;
                        tb &= tb - 1;
                    }
                    if (setflag && w >= (LRANK >> 6)) g_flagB = 1;
                }
                cnt += take;
                cur |= bulk;
                if (cnt >= KOUT) break;
            }
            if (!sup) break;
            int bpos = __ffsll((long long)sup) - 1;
            int i = (w << 6) + bpos;
            if (lane == 0) {
                sel[cnt] = i;
                if (setflag && i >= LRANK) g_flagB = 1;
            }
            cnt++;
            cur |= (1ull << bpos);
            if (cnt >= KOUT) break;
            const u64* rowp = mask + (size_t)i * WSTRIDE;
            u64 r0 = __ldg(rowp + lane);
            u64 r1 = __ldg(rowp + lane + 32);
            u64 r2 = (lane + 64 < WORDS) ? __ldg(rowp + lane + 64) : 0ull;
            u64 rcur = __ldg(rowp + w);
            rm0 |= r0; rm1 |= r1; rm2 |= r2;
            cur |= rcur;
            u64 pf = ~cur & hasw;
            #pragma unroll
            for (int c = 0; c < 2; c++) {
                if (!pf) break;
                int nb = __ffsll((long long)pf) - 1;
                pf &= pf - 1;
                const char* p = (const char*)(mask + (size_t)((w << 6) + nb) * WSTRIDE);
                if ((lane >> 3) == c && (lane & 7) < 6)
                    asm volatile("prefetch.global.L1 [%0];" :: "l"(p + (lane & 7) * 128));
            }
        }
    }
    __syncwarp();

    float4* o = (float4*)(out + (size_t)b * KOUT * 4);
    for (int r = lane; r < KOUT; r += 32) {
        float4 v = make_float4(0.f, 0.f, 0.f, 0.f);
        if (r < cnt) v = g_boxes[b][sel[r]];
        o[r] = v;
    }
}

// ---------------- K8: primary reduce (1 warp per batch) ----------------
__global__ void k_reduce(float* __restrict__ out) {
    __shared__ int sel[KOUT];
    reduce_core(blockIdx.x, threadIdx.x, sel, out, 1);
}

// ---------------- K9: gated fallback B — zero tail, tail pairs, full redo ---------
__global__ void k_fallbackB(float* __restrict__ out) {
    if (!g_flagB) return;
    int t = threadIdx.x;   // 1024
    const int n = BATCH * (KPRE - LRANK) * WSTRIDE;
    for (int i = t; i < n; i += 1024) {
        int b = i / ((KPRE - LRANK) * WSTRIDE);
        int rem = i - b * ((KPRE - LRANK) * WSTRIDE);
        g_mask[b][LRANK + rem / WSTRIDE][rem % WSTRIDE] = 0ull;
    }
    __syncthreads();
    __shared__ float4 sb4[64];
    __shared__ float  sar[64];
    __shared__ int    srk[64];
    int row = t & 63;
    int half = (t >> 6) & 1;
    for (int b = 0; b < BATCH; b++) {
        for (int ta = HTILES; ta < TILES; ta++) {
            float4 aA = g_aabb[b][ta];
            float4 bi = make_float4(0, 0, 0, 0);
            float ai = 0.f; int ra = 0;
            if (t < 128) {
                int sa = ta * 64 + row;
                bi = g_sbox[b][sa]; ai = g_sarea[b][sa]; ra = g_srank[b][sa];
            }
            for (int tb = ta; tb < TILES; tb++) {
                float4 aB = g_aabb[b][tb];
                bool tok = (aA.z > aB.x && aB.z > aA.x && aA.w > aB.y && aB.w > aA.y);
                __syncthreads();
                if (tok && t < 64) {
                    int s = tb * 64 + t;
                    sb4[t] = g_sbox[b][s]; sar[t] = g_sarea[b][s]; srk[t] = g_srank[b][s];
                }
                __syncthreads();
                if (!tok || t >= 128) continue;
                if (!(bi.z > aB.x && aB.z > bi.x && bi.w > aB.y && aB.w > bi.y)) continue;
                bool diag = (ta == tb);
                for (int jj = half * 32; jj < half * 32 + 32; ++jj) {
                    if (diag && jj <= row) continue;
                    float4 bj = sb4[jj];
                    float yy1 = fmaxf(bi.x, bj.x);
                    float xx1 = fmaxf(bi.y, bj.y);
                    float yy2 = fminf(bi.z, bj.z);
                    float xx2 = fminf(bi.w, bj.w);
                    float dh = __fsub_rn(yy2, yy1);
                    float dw = __fsub_rn(xx2, xx1);
                    if (dh > 0.f && dw > 0.f) {
                        float inter = __fmul_rn(dh, dw);
                        float u = __fsub_rn(__fadd_rn(ai, sar[jj]), inter);
                        if (u > 0.f) {
                            bool sup;
                            if (inter > __fmul_rn(0.71f, u)) sup = true;
                            else if (inter >= __fmul_rn(0.69f, u)) sup = __fdiv_rn(inter, u) > 0.7f;
                            else sup = false;
                            if (sup) {
                                int rb = srk[jj];
                                int rmin = ra < rb ? ra : rb;
                                int rmax = ra < rb ? rb : ra;
                                atomicOr(&g_mask[b][rmin][rmax >> 6], 1ull << (rmax & 63));
                                atomicOr(&g_rowbits[b][rmin >> 6], 1ull << (rmin & 63));
                            }
                        }
                    }
                }
            }
        }
    }
    __threadfence();
    __syncthreads();
    __shared__ int sel[BATCH][KOUT];
    int wid = t >> 5, lane = t & 31;
    if (wid < BATCH) reduce_core(wid, lane, sel[wid], out, 0);
}

// ---------------- launch (11 graph nodes) ----------------
extern "C" void kernel_launch(void* const* d_in, const int* in_sizes, int n_in,
                              void* d_out, int out_size) {
    const float4* scores4 = (const float4*)d_in[0];
    const float4* deltas  = (const float4*)d_in[1];
    const float4* anchors = (const float4*)d_in[2];
    float* out = (float*)d_out;

    k_zero<<<512, 1024>>>();                    // 1
    {
        dim3 g(512, BATCH);                     // 2 (more CTAs in flight for BW)
        k_compactS<<<g, 256>>>(scores4);
    }
    k_fallbackA<<<1, 1024>>>(scores4);          // 3 (self-gated)
    {
        dim3 g(NCHUNK2, BATCH);
        k_sort2048<<<g, 1024>>>();              // 4
    }
    {
        dim3 g(SORT_N / 256, BATCH);
        k_mergepass<<<g, 256>>>(0, 2048);       // 5: cand2 -> cand
        k_mergepass<<<g, 256>>>(1, 4096);       // 6: cand -> cand2 (final sorted)
    }
    {
        dim3 g((KPRE + 255) / 256, BATCH);
        k_boxes<<<g, 256>>>(deltas, anchors);   // 7
    }
    k_spatial<<<BATCH, 1024>>>();               // 8
    {
        dim3 g(TILES, HTILES, BATCH);
        k_pairs<<<g, 128>>>();                  // 9
    }
    k_reduce<<<BATCH, 32>>>(out);               // 10
    k_fallbackB<<<1, 1024>>>(out);              // 11 (gated)
}